// round 15
// baseline (speedup 1.0000x reference)
#include <cuda_runtime.h>

// MedSegNet texture features, algebraically folded (theta=1):
//   g   = cl*ln(cl), cl = max(p,1e-6); entropy separable via hg built at load.
//   3x3 box sums of p, p^2 via packed f32x2 vertical column sums.
//   ssq = P2 - S*mean; contrast*e^-.5 = min(max(ssq*67392.295,1e-4), 8/9*e^-.5)
//   M(f) = fmaxf(f*exp(-0.5), 1e-4)
// Round 15: R12 body (stable best, 33.2us) inside a persistent grid-stride
// loop: 888 blocks (148 SMs x 6 resident) iterate over the 4096 tiles.
// Removes tail-wave quantization + per-block launch overhead; body unchanged.

#define H 128
#define W 128
#define NPLANES 512        // B*C = 8*64
#define TILE_H 16
#define TILES_X (H / TILE_H)            // 8
#define NTILES (TILES_X * NPLANES)      // 4096
#define NBLOCKS 888                     // 148 SMs * 6 resident blocks
#define SH (TILE_H + 2)
#define SW2 132            // sp row stride (16B-aligned rows)
#define GPAD (-1.3815511e-5f)   // 1e-6 * ln(1e-6)

typedef unsigned long long u64;

__device__ __forceinline__ u64 add2(u64 a, u64 b) {
    u64 d; asm("add.rn.f32x2 %0,%1,%2;" : "=l"(d) : "l"(a), "l"(b)); return d;
}
__device__ __forceinline__ u64 mul2(u64 a, u64 b) {
    u64 d; asm("mul.rn.f32x2 %0,%1,%2;" : "=l"(d) : "l"(a), "l"(b)); return d;
}
__device__ __forceinline__ u64 fma2(u64 a, u64 b, u64 c) {
    u64 d; asm("fma.rn.f32x2 %0,%1,%2,%3;" : "=l"(d) : "l"(a), "l"(b), "l"(c)); return d;
}
__device__ __forceinline__ float2 unpk(u64 v) {
    float2 r; asm("mov.b64 {%0,%1},%2;" : "=f"(r.x), "=f"(r.y) : "l"(v)); return r;
}
__device__ __forceinline__ u64 pk(float x, float y) {
    u64 d; asm("mov.b64 %0,{%1,%2};" : "=l"(d) : "f"(x), "f"(y)); return d;
}

__global__ __launch_bounds__(256)
void medseg_kernel(const float* __restrict__ x, float* __restrict__ out) {
    __shared__ __align__(16) float sp[SH][SW2];   // sp[r][j] = p[r-1][j-1]
    __shared__ __align__(16) float shg[SH][128];  // shg[r][c] = hsum g at col c

    const int tx = threadIdx.x;                // 0..31
    const int ty = threadIdx.y;                // 0..7

    const float INV9 = 1.0f / 9.0f;
    const float EMH  = 0.60653066f;            // exp(-0.5)
    const float C89E = 0.53913838f;            // (8/9)*exp(-0.5)
    const float CCLP = 67392.295f;             // (1e6/9)*exp(-0.5)
    const float CE9  = 0.067392295f;           // exp(-0.5)/9

    for (int tile = blockIdx.x; tile < NTILES; tile += NBLOCKS) {
        const int bc = tile >> 3;                      // plane
        const int rowBase = (tile & 7) * TILE_H;       // row strip

        const float* __restrict__ plane = x + (size_t)bc * (H * W);

        // ---- load phase: warp ty fills shared rows ty, ty+8, ty+16 ----
        #pragma unroll
        for (int rep = 0; rep < 3; rep++) {
            const int sr = ty + rep * 8;
            if (sr < SH) {
                const int gr = rowBase + sr - 1;
                float4 v, gv;
                if ((unsigned)gr < (unsigned)H) {      // warp-uniform branch
                    v = *(const float4*)(plane + gr * W + 4 * tx);
                    const float c0 = fmaxf(v.x, 1e-6f), c1 = fmaxf(v.y, 1e-6f);
                    const float c2 = fmaxf(v.z, 1e-6f), c3 = fmaxf(v.w, 1e-6f);
                    gv.x = c0 * __logf(c0);
                    gv.y = c1 * __logf(c1);
                    gv.z = c2 * __logf(c2);
                    gv.w = c3 * __logf(c3);
                } else {
                    v  = make_float4(0.f, 0.f, 0.f, 0.f);
                    gv = make_float4(GPAD, GPAD, GPAD, GPAD);
                }
                float pw = __shfl_up_sync(0xffffffffu, v.w, 1);
                float gw = __shfl_up_sync(0xffffffffu, gv.w, 1);
                float gn = __shfl_down_sync(0xffffffffu, gv.x, 1);
                if (tx == 0)  { pw = 0.0f; gw = GPAD; }   // global col -1 pad
                if (tx == 31) { gn = GPAD; }              // global col 128 pad

                *(float4*)&sp[sr][4 * tx] = make_float4(pw, v.x, v.y, v.z);
                if (tx == 31)
                    *(float2*)&sp[sr][128] = make_float2(v.w, 0.0f);

                float4 h;
                h.x = gw   + gv.x + gv.y;
                h.y = gv.x + gv.y + gv.z;
                h.z = gv.y + gv.z + gv.w;
                h.w = gv.z + gv.w + gn;
                *(float4*)&shg[sr][4 * tx] = h;
            }
        }
        __syncthreads();

        float* __restrict__ outp = out + (size_t)(4 * bc) * (H * W);

        #pragma unroll
        for (int rr = 0; rr < 2; rr++) {
            const int lr = ty + rr * 8;            // local output row
            const int sr = lr + 1;
            const int sc = 4 * tx;                 // sp col of (global col 4tx - 1)
            float* op = outp + (rowBase + lr) * W + 4 * tx;

            // ---- entropy: separable + packed vertical adds ----
            {
                const ulonglong2 H0 = *(const ulonglong2*)&shg[sr - 1][4 * tx];
                const ulonglong2 H1 = *(const ulonglong2*)&shg[sr    ][4 * tx];
                const ulonglong2 H2 = *(const ulonglong2*)&shg[sr + 1][4 * tx];
                const u64 nce9 = pk(-CE9, -CE9);
                const float2 e01 = unpk(mul2(add2(add2(H0.x, H1.x), H2.x), nce9));
                const float2 e23 = unpk(mul2(add2(add2(H0.y, H1.y), H2.y), nce9));
                float4 m2;
                m2.x = fmaxf(e01.x, 1e-4f);
                m2.y = fmaxf(e01.y, 1e-4f);
                m2.z = fmaxf(e23.x, 1e-4f);
                m2.w = fmaxf(e23.y, 1e-4f);
                *(float4*)(op + 2 * H * W) = m2;
            }

            // ---- p rows (packed) ----
            const ulonglong2 Pa0 = *(const ulonglong2*)&sp[sr - 1][sc];
            const u64        Pb0 = *(const u64*)&sp[sr - 1][sc + 4];
            const ulonglong2 Pa1 = *(const ulonglong2*)&sp[sr    ][sc];
            const u64        Pb1 = *(const u64*)&sp[sr    ][sc + 4];
            const ulonglong2 Pa2 = *(const ulonglong2*)&sp[sr + 1][sc];
            const u64        Pb2 = *(const u64*)&sp[sr + 1][sc + 4];

            // p^2 column sums first, retired immediately into P2v + energy store
            float P2v[4];
            {
                const float2 cq01 = unpk(fma2(Pa0.x, Pa0.x, fma2(Pa1.x, Pa1.x, mul2(Pa2.x, Pa2.x))));
                const float2 cq23 = unpk(fma2(Pa0.y, Pa0.y, fma2(Pa1.y, Pa1.y, mul2(Pa2.y, Pa2.y))));
                const float2 cq45 = unpk(fma2(Pb0,   Pb0,   fma2(Pb1,   Pb1,   mul2(Pb2,   Pb2))));
                float4 m1;
                P2v[0] = cq01.x + cq01.y + cq23.x;  m1.x = fmaxf(P2v[0] * CE9, 1e-4f);
                P2v[1] = cq01.y + cq23.x + cq23.y;  m1.y = fmaxf(P2v[1] * CE9, 1e-4f);
                P2v[2] = cq23.x + cq23.y + cq45.x;  m1.z = fmaxf(P2v[2] * CE9, 1e-4f);
                P2v[3] = cq23.y + cq45.x + cq45.y;  m1.w = fmaxf(P2v[3] * CE9, 1e-4f);
                *(float4*)(op + H * W) = m1;
            }

            // p column sums
            const float2 cp01 = unpk(add2(add2(Pa0.x, Pa1.x), Pa2.x));
            const float2 cp23 = unpk(add2(add2(Pa0.y, Pa1.y), Pa2.y));
            const float2 cp45 = unpk(add2(add2(Pb0,   Pb1),   Pb2));
            const float cp[6] = {cp01.x, cp01.y, cp23.x, cp23.y, cp45.x, cp45.y};

            // scalar p for the non-separable sab pass (aliases of packed regs)
            float p[3][6];
            {
                float2 t;
                t = unpk(Pa0.x); p[0][0]=t.x; p[0][1]=t.y;
                t = unpk(Pa0.y); p[0][2]=t.x; p[0][3]=t.y;
                t = unpk(Pb0);   p[0][4]=t.x; p[0][5]=t.y;
                t = unpk(Pa1.x); p[1][0]=t.x; p[1][1]=t.y;
                t = unpk(Pa1.y); p[1][2]=t.x; p[1][3]=t.y;
                t = unpk(Pb1);   p[1][4]=t.x; p[1][5]=t.y;
                t = unpk(Pa2.x); p[2][0]=t.x; p[2][1]=t.y;
                t = unpk(Pa2.y); p[2][2]=t.x; p[2][3]=t.y;
                t = unpk(Pb2);   p[2][4]=t.x; p[2][5]=t.y;
            }

            // contrast + homogeneity
            float mcv[4], mhv[4];
            #pragma unroll
            for (int i = 0; i < 4; i++) {
                const float S    = cp[i] + cp[i+1] + cp[i+2];
                const float mean = S * INV9;
                const float ssq  = fmaf(-S, mean, P2v[i]);   // sum (p-mean)^2

                float sab = 0.0f;                             // sum |p-mean|
                #pragma unroll
                for (int r = 0; r < 3; r++) {
                    sab += fabsf(p[r][i]     - mean);
                    sab += fabsf(p[r][i + 1] - mean);
                    sab += fabsf(p[r][i + 2] - mean);
                }

                mcv[i] = fminf(fmaxf(ssq * CCLP, 1e-4f), C89E);
                const float t = fmaf(sab, INV9, 1.000001f);
                mhv[i] = fmaxf(__fdividef(EMH, t), 1e-4f);
            }
            *(float4*)(op)             = make_float4(mcv[0], mcv[1], mcv[2], mcv[3]);
            *(float4*)(op + 3 * H * W) = make_float4(mhv[0], mhv[1], mhv[2], mhv[3]);
        }
        __syncthreads();   // protect smem before next tile's load phase
    }
}

extern "C" void kernel_launch(void* const* d_in, const int* in_sizes, int n_in,
                              void* d_out, int out_size) {
    const float* x = (const float*)d_in[0];
    float* out = (float*)d_out;
    dim3 block(32, 8);
    medseg_kernel<<<NBLOCKS, block>>>(x, out);
}

// round 16
// speedup vs baseline: 1.2765x; 1.2765x over previous
#include <cuda_runtime.h>

// MedSegNet texture features, algebraically folded (theta=1):
//   g   = cl*ln(cl), cl = max(p,1e-6); entropy separable via hg built at load.
//   3x3 box sums of p, p^2 via packed f32x2 vertical column sums.
//   ssq = P2 - S*mean; contrast*e^-.5 = min(max(ssq*67392.295,1e-4), 8/9*e^-.5)
//   M(f) = fmaxf(f*exp(-0.5), 1e-4)
// FINAL (== Round 12; session best 33.2us wall / 28.9us kernel, reproduced 3x):
//   32x8 block, TILE_H=16, 2 output rows x 4 px per thread,
//   shuffle-built vectorized load phase (LDG.128 + aligned STS.128),
//   separable entropy (hg precomputed horizontally at load),
//   packed f32x2 column sums, natural register allocation (regs=40).
// Measured dead ends: reg caps (R5/R11), row pairing (R4), 1 row/thread (R7),
// TILE_H=32 (R9), cache hints (R13), persistent grid (R15).

#define H 128
#define W 128
#define NPLANES 512        // B*C = 8*64
#define TILE_H 16
#define SH (TILE_H + 2)
#define SW2 132            // sp row stride (16B-aligned rows)
#define GPAD (-1.3815511e-5f)   // 1e-6 * ln(1e-6)

typedef unsigned long long u64;

__device__ __forceinline__ u64 add2(u64 a, u64 b) {
    u64 d; asm("add.rn.f32x2 %0,%1,%2;" : "=l"(d) : "l"(a), "l"(b)); return d;
}
__device__ __forceinline__ u64 mul2(u64 a, u64 b) {
    u64 d; asm("mul.rn.f32x2 %0,%1,%2;" : "=l"(d) : "l"(a), "l"(b)); return d;
}
__device__ __forceinline__ u64 fma2(u64 a, u64 b, u64 c) {
    u64 d; asm("fma.rn.f32x2 %0,%1,%2,%3;" : "=l"(d) : "l"(a), "l"(b), "l"(c)); return d;
}
__device__ __forceinline__ float2 unpk(u64 v) {
    float2 r; asm("mov.b64 {%0,%1},%2;" : "=f"(r.x), "=f"(r.y) : "l"(v)); return r;
}
__device__ __forceinline__ u64 pk(float x, float y) {
    u64 d; asm("mov.b64 %0,{%1,%2};" : "=l"(d) : "f"(x), "f"(y)); return d;
}

__global__ __launch_bounds__(256)
void medseg_kernel(const float* __restrict__ x, float* __restrict__ out) {
    const int bc = blockIdx.y;
    const int rowBase = blockIdx.x * TILE_H;

    __shared__ __align__(16) float sp[SH][SW2];   // sp[r][j] = p[r-1][j-1]
    __shared__ __align__(16) float shg[SH][128];  // shg[r][c] = hsum g at col c

    const int tx = threadIdx.x;                // 0..31
    const int ty = threadIdx.y;                // 0..7

    const float* __restrict__ plane = x + (size_t)bc * (H * W);

    // ---- load phase: warp ty fills shared rows ty, ty+8, ty+16 ----
    #pragma unroll
    for (int rep = 0; rep < 3; rep++) {
        const int sr = ty + rep * 8;
        if (sr < SH) {
            const int gr = rowBase + sr - 1;
            float4 v, gv;
            if ((unsigned)gr < (unsigned)H) {      // warp-uniform branch
                v = *(const float4*)(plane + gr * W + 4 * tx);
                const float c0 = fmaxf(v.x, 1e-6f), c1 = fmaxf(v.y, 1e-6f);
                const float c2 = fmaxf(v.z, 1e-6f), c3 = fmaxf(v.w, 1e-6f);
                gv.x = c0 * __logf(c0);
                gv.y = c1 * __logf(c1);
                gv.z = c2 * __logf(c2);
                gv.w = c3 * __logf(c3);
            } else {
                v  = make_float4(0.f, 0.f, 0.f, 0.f);
                gv = make_float4(GPAD, GPAD, GPAD, GPAD);
            }
            float pw = __shfl_up_sync(0xffffffffu, v.w, 1);
            float gw = __shfl_up_sync(0xffffffffu, gv.w, 1);
            float gn = __shfl_down_sync(0xffffffffu, gv.x, 1);
            if (tx == 0)  { pw = 0.0f; gw = GPAD; }   // global col -1 pad
            if (tx == 31) { gn = GPAD; }              // global col 128 pad

            *(float4*)&sp[sr][4 * tx] = make_float4(pw, v.x, v.y, v.z);
            if (tx == 31)
                *(float2*)&sp[sr][128] = make_float2(v.w, 0.0f);

            float4 h;
            h.x = gw   + gv.x + gv.y;
            h.y = gv.x + gv.y + gv.z;
            h.z = gv.y + gv.z + gv.w;
            h.w = gv.z + gv.w + gn;
            *(float4*)&shg[sr][4 * tx] = h;
        }
    }
    __syncthreads();

    const float INV9 = 1.0f / 9.0f;
    const float EMH  = 0.60653066f;            // exp(-0.5)
    const float C89E = 0.53913838f;            // (8/9)*exp(-0.5)
    const float CCLP = 67392.295f;             // (1e6/9)*exp(-0.5)
    const float CE9  = 0.067392295f;           // exp(-0.5)/9

    float* __restrict__ outp = out + (size_t)(4 * bc) * (H * W);

    #pragma unroll
    for (int rr = 0; rr < 2; rr++) {
        const int lr = ty + rr * 8;            // local output row
        const int sr = lr + 1;
        const int sc = 4 * tx;                 // sp col of (global col 4tx - 1)
        float* op = outp + (rowBase + lr) * W + 4 * tx;

        // ---- entropy: separable + packed vertical adds ----
        {
            const ulonglong2 H0 = *(const ulonglong2*)&shg[sr - 1][4 * tx];
            const ulonglong2 H1 = *(const ulonglong2*)&shg[sr    ][4 * tx];
            const ulonglong2 H2 = *(const ulonglong2*)&shg[sr + 1][4 * tx];
            const u64 nce9 = pk(-CE9, -CE9);
            const float2 e01 = unpk(mul2(add2(add2(H0.x, H1.x), H2.x), nce9));
            const float2 e23 = unpk(mul2(add2(add2(H0.y, H1.y), H2.y), nce9));
            float4 m2;
            m2.x = fmaxf(e01.x, 1e-4f);
            m2.y = fmaxf(e01.y, 1e-4f);
            m2.z = fmaxf(e23.x, 1e-4f);
            m2.w = fmaxf(e23.y, 1e-4f);
            *(float4*)(op + 2 * H * W) = m2;
        }

        // ---- p rows (packed) ----
        const ulonglong2 Pa0 = *(const ulonglong2*)&sp[sr - 1][sc];
        const u64        Pb0 = *(const u64*)&sp[sr - 1][sc + 4];
        const ulonglong2 Pa1 = *(const ulonglong2*)&sp[sr    ][sc];
        const u64        Pb1 = *(const u64*)&sp[sr    ][sc + 4];
        const ulonglong2 Pa2 = *(const ulonglong2*)&sp[sr + 1][sc];
        const u64        Pb2 = *(const u64*)&sp[sr + 1][sc + 4];

        // p^2 column sums first, retired immediately into P2v + energy store
        float P2v[4];
        {
            const float2 cq01 = unpk(fma2(Pa0.x, Pa0.x, fma2(Pa1.x, Pa1.x, mul2(Pa2.x, Pa2.x))));
            const float2 cq23 = unpk(fma2(Pa0.y, Pa0.y, fma2(Pa1.y, Pa1.y, mul2(Pa2.y, Pa2.y))));
            const float2 cq45 = unpk(fma2(Pb0,   Pb0,   fma2(Pb1,   Pb1,   mul2(Pb2,   Pb2))));
            float4 m1;
            P2v[0] = cq01.x + cq01.y + cq23.x;  m1.x = fmaxf(P2v[0] * CE9, 1e-4f);
            P2v[1] = cq01.y + cq23.x + cq23.y;  m1.y = fmaxf(P2v[1] * CE9, 1e-4f);
            P2v[2] = cq23.x + cq23.y + cq45.x;  m1.z = fmaxf(P2v[2] * CE9, 1e-4f);
            P2v[3] = cq23.y + cq45.x + cq45.y;  m1.w = fmaxf(P2v[3] * CE9, 1e-4f);
            *(float4*)(op + H * W) = m1;
        }

        // p column sums
        const float2 cp01 = unpk(add2(add2(Pa0.x, Pa1.x), Pa2.x));
        const float2 cp23 = unpk(add2(add2(Pa0.y, Pa1.y), Pa2.y));
        const float2 cp45 = unpk(add2(add2(Pb0,   Pb1),   Pb2));
        const float cp[6] = {cp01.x, cp01.y, cp23.x, cp23.y, cp45.x, cp45.y};

        // scalar p for the non-separable sab pass (aliases of packed regs)
        float p[3][6];
        {
            float2 t;
            t = unpk(Pa0.x); p[0][0]=t.x; p[0][1]=t.y;
            t = unpk(Pa0.y); p[0][2]=t.x; p[0][3]=t.y;
            t = unpk(Pb0);   p[0][4]=t.x; p[0][5]=t.y;
            t = unpk(Pa1.x); p[1][0]=t.x; p[1][1]=t.y;
            t = unpk(Pa1.y); p[1][2]=t.x; p[1][3]=t.y;
            t = unpk(Pb1);   p[1][4]=t.x; p[1][5]=t.y;
            t = unpk(Pa2.x); p[2][0]=t.x; p[2][1]=t.y;
            t = unpk(Pa2.y); p[2][2]=t.x; p[2][3]=t.y;
            t = unpk(Pb2);   p[2][4]=t.x; p[2][5]=t.y;
        }

        // contrast + homogeneity
        float mcv[4], mhv[4];
        #pragma unroll
        for (int i = 0; i < 4; i++) {
            const float S    = cp[i] + cp[i+1] + cp[i+2];
            const float mean = S * INV9;
            const float ssq  = fmaf(-S, mean, P2v[i]);   // sum (p-mean)^2

            float sab = 0.0f;                             // sum |p-mean|
            #pragma unroll
            for (int r = 0; r < 3; r++) {
                sab += fabsf(p[r][i]     - mean);
                sab += fabsf(p[r][i + 1] - mean);
                sab += fabsf(p[r][i + 2] - mean);
            }

            mcv[i] = fminf(fmaxf(ssq * CCLP, 1e-4f), C89E);
            const float t = fmaf(sab, INV9, 1.000001f);
            mhv[i] = fmaxf(__fdividef(EMH, t), 1e-4f);
        }
        *(float4*)(op)             = make_float4(mcv[0], mcv[1], mcv[2], mcv[3]);
        *(float4*)(op + 3 * H * W) = make_float4(mhv[0], mhv[1], mhv[2], mhv[3]);
    }
}

extern "C" void kernel_launch(void* const* d_in, const int* in_sizes, int n_in,
                              void* d_out, int out_size) {
    const float* x = (const float*)d_in[0];
    float* out = (float*)d_out;
    dim3 block(32, 8);
    dim3 grid(H / TILE_H, NPLANES);   // (8, 512)
    medseg_kernel<<<grid, block>>>(x, out);
}